// round 2
// baseline (speedup 1.0000x reference)
#include <cuda_runtime.h>
#include <math.h>

// Problem constants (fixed by the dataset)
#define S_ 1024
#define H_ 768
#define L_ 50
#define SW_ 10
#define D_ 2304            // 3*H
#define KGCN (L_*H_)       // 38400
#define MAXSPAN 9216       // multiple of 128, >= 9171
#define MAXTOPK 1024

// GEMM tiling
#define BM 128
#define BN 128
#define BK 8
#define SPLITK 12          // 38400/12 = 3200 per split

// ---------------- device scratch (zero-initialized at module load) -------------
__device__ __align__(16) float g_agg[(size_t)S_*L_*H_];   // 157 MB
__device__ __align__(16) float g_cnt[S_*L_];
__device__ __align__(16) float g_gcn[S_*H_];
__device__ __align__(16) float g_emb[S_*H_];
__device__ __align__(16) float g_pscore[S_];
__device__ __align__(16) float g_spanvec[(size_t)MAXSPAN*D_]; // 85 MB; pad rows stay 0
__device__ __align__(16) float g_mscore[MAXSPAN];
__device__ int   g_topk[MAXTOPK];
__device__ float g_si[MAXTOPK];
__device__ float g_sj[MAXTOPK];

// ---------------- zero kernels -------------------------------------------------
__global__ void zero_agg_kernel() {
    size_t idx = (size_t)blockIdx.x * blockDim.x + threadIdx.x;
    size_t stride = (size_t)gridDim.x * blockDim.x;
    float4* p = reinterpret_cast<float4*>(g_agg);
    size_t n4 = (size_t)S_ * L_ * H_ / 4;
    float4 z = make_float4(0.f, 0.f, 0.f, 0.f);
    for (size_t i = idx; i < n4; i += stride) p[i] = z;
}

__global__ void zero_small_kernel() {
    int idx = blockIdx.x * blockDim.x + threadIdx.x;
    int stride = gridDim.x * blockDim.x;
    for (int i = idx; i < S_*H_; i += stride) g_gcn[i] = 0.f;
    for (int i = idx; i < S_*L_; i += stride) g_cnt[i] = 0.f;
}

// ---------------- edge scatter: agg[tgt,lbl,:] += x[src,:], cnt[tgt,lbl]++ -----
__global__ void scatter_kernel(const float* __restrict__ x,
                               const int* __restrict__ edges) {
    int e = blockIdx.x;
    int src = edges[e*3+0];
    int tgt = edges[e*3+1];
    int lbl = edges[e*3+2];
    float* dst = &g_agg[((size_t)tgt * L_ + lbl) * H_];
    const float* srow = &x[(size_t)src * H_];
    for (int h = threadIdx.x; h < H_; h += blockDim.x)
        atomicAdd(&dst[h], srow[h]);
    if (threadIdx.x == 0)
        atomicAdd(&g_cnt[tgt * L_ + lbl], 1.0f);
}

// ---------------- GEMM1: g_gcn(1024x768) += agg(1024x38400) @ gcn_W ------------
__global__ __launch_bounds__(256)
void gemm_gcn_kernel(const float* __restrict__ W) {
    __shared__ float As[BK][BM];
    __shared__ float Bs[BK][BN];
    int tid = threadIdx.x;
    int bx = blockIdx.x;          // N blocks: 6
    int by = blockIdx.y;          // M blocks: 8
    int bz = blockIdx.z;          // split-K
    const int Kc = KGCN / SPLITK; // 3200
    int kbase = bz * Kc;

    int arow = tid >> 1,  acol = (tid & 1) * 4;
    int brow = tid >> 5,  bcol = (tid & 31) * 4;
    int ty = tid >> 4,    tx = tid & 15;

    float acc[8][8];
#pragma unroll
    for (int i = 0; i < 8; i++)
#pragma unroll
        for (int j = 0; j < 8; j++) acc[i][j] = 0.f;

    const float* Aptr = &g_agg[(size_t)(by*BM + arow) * KGCN];
    float4 pa = *(const float4*)&Aptr[kbase + acol];
    float4 pb = *(const float4*)&W[(size_t)(kbase + brow) * H_ + bx*BN + bcol];

    int iters = Kc / BK; // 400
    for (int kt = 0; kt < iters; kt++) {
        As[acol+0][arow] = pa.x;
        As[acol+1][arow] = pa.y;
        As[acol+2][arow] = pa.z;
        As[acol+3][arow] = pa.w;
        *(float4*)&Bs[brow][bcol] = pb;
        __syncthreads();
        if (kt + 1 < iters) {
            int k0 = kbase + (kt+1)*BK;
            pa = *(const float4*)&Aptr[k0 + acol];
            pb = *(const float4*)&W[(size_t)(k0 + brow) * H_ + bx*BN + bcol];
        }
#pragma unroll
        for (int kk = 0; kk < BK; kk++) {
            float4 a0 = *(float4*)&As[kk][ty*4];
            float4 a1 = *(float4*)&As[kk][ty*4+64];
            float4 b0 = *(float4*)&Bs[kk][tx*4];
            float4 b1 = *(float4*)&Bs[kk][tx*4+64];
            float a[8] = {a0.x,a0.y,a0.z,a0.w,a1.x,a1.y,a1.z,a1.w};
            float b[8] = {b0.x,b0.y,b0.z,b0.w,b1.x,b1.y,b1.z,b1.w};
#pragma unroll
            for (int i = 0; i < 8; i++)
#pragma unroll
                for (int j = 0; j < 8; j++)
                    acc[i][j] += a[i]*b[j];
        }
        __syncthreads();
    }

#pragma unroll
    for (int i = 0; i < 8; i++) {
        int r = by*BM + ((i < 4) ? (ty*4 + i) : (64 + ty*4 + i - 4));
#pragma unroll
        for (int j = 0; j < 8; j++) {
            int c = bx*BN + ((j < 4) ? (tx*4 + j) : (64 + tx*4 + j - 4));
            atomicAdd(&g_gcn[r*H_ + c], acc[i][j]);
        }
    }
}

// ---------------- GCN epilogue: emb = x + relu((gcn + cnt@gcn_b)/deg) ----------
__global__ void gcn_finish_kernel(const float* __restrict__ x,
                                  const float* __restrict__ gcn_b) {
    int s = blockIdx.x;
    __shared__ float scnt[L_];
    if (threadIdx.x < L_) scnt[threadIdx.x] = g_cnt[s*L_ + threadIdx.x];
    __syncthreads();
    float deg = 0.f;
#pragma unroll
    for (int l = 0; l < L_; l++) deg += scnt[l];
    deg = fmaxf(deg, 1.0f);
    float inv = 1.0f / deg;
    for (int c = threadIdx.x; c < H_; c += blockDim.x) {
        float bias = 0.f;
#pragma unroll 10
        for (int l = 0; l < L_; l++) bias += scnt[l] * gcn_b[l*H_ + c];
        float v = (g_gcn[s*H_ + c] + bias) * inv;
        v = v > 0.f ? v : 0.f;
        g_emb[s*H_ + c] = x[s*H_ + c] + v;
    }
}

// ---------------- per-position attention score: pscore[s] = emb[s]·attn_w + b --
__global__ void row_score_kernel(const float* __restrict__ attn_w,
                                 const float* __restrict__ attn_b) {
    int warp = threadIdx.x >> 5;
    int lane = threadIdx.x & 31;
    int s = blockIdx.x * 8 + warp;
    if (s >= S_) return;
    float p = 0.f;
    for (int h = lane; h < H_; h += 32)
        p += g_emb[s*H_ + h] * attn_w[h];
#pragma unroll
    for (int o = 16; o > 0; o >>= 1)
        p += __shfl_xor_sync(0xffffffffu, p, o);
    if (lane == 0) g_pscore[s] = p + attn_b[0];
}

// ---------------- span attention + span_vec assembly (warp per span) -----------
__global__ void span_kernel(const int* __restrict__ starts,
                            const int* __restrict__ ends, int nspan) {
    int gwarp = (blockIdx.x * blockDim.x + threadIdx.x) >> 5;
    int lane = threadIdx.x & 31;
    if (gwarp >= nspan) return;
    int st = starts[gwarp];
    int en = ends[gwarp];

    float sc[SW_];
    int   pc[SW_];
    float m = -3.4e38f;
#pragma unroll
    for (int w = 0; w < SW_; w++) {
        int pos = st + w;
        pc[w] = pos < (S_-1) ? pos : (S_-1);
        float sv = g_pscore[pc[w]];
        if (pos > en) sv = -1e9f;
        sc[w] = sv;
        m = fmaxf(m, sv);
    }
    float denom = 0.f;
#pragma unroll
    for (int w = 0; w < SW_; w++) { sc[w] = expf(sc[w] - m); denom += sc[w]; }
    float inv = 1.0f / denom;

    float* out = &g_spanvec[(size_t)gwarp * D_];
    for (int h = lane; h < H_; h += 32) {
        float o = 0.f;
#pragma unroll
        for (int w = 0; w < SW_; w++)
            o += sc[w] * g_emb[pc[w]*H_ + h];
        out[h]        = g_emb[st*H_ + h];
        out[H_ + h]   = g_emb[en*H_ + h];
        out[2*H_ + h] = o * inv;
    }
}

// ---------------- mention scores init ------------------------------------------
__global__ void init_mscore_kernel(const float* __restrict__ ms_b2, int nspan) {
    int i = blockIdx.x * blockDim.x + threadIdx.x;
    if (i < nspan) g_mscore[i] = ms_b2[0];
}

// -------- GEMM2: hdn = relu(spanvec @ ms_W1 + b1); mscore += hdn @ ms_W2 -------
__global__ __launch_bounds__(256)
void gemm_mention_kernel(const float* __restrict__ W1,
                         const float* __restrict__ b1,
                         const float* __restrict__ W2, int nspan) {
    __shared__ float As[BK][BM];
    __shared__ float Bs[BK][BN];
    int tid = threadIdx.x;
    int bx = blockIdx.x;   // N blocks: 18
    int by = blockIdx.y;   // M blocks: 72

    int arow = tid >> 1,  acol = (tid & 1) * 4;
    int brow = tid >> 5,  bcol = (tid & 31) * 4;
    int ty = tid >> 4,    tx = tid & 15;

    float acc[8][8];
#pragma unroll
    for (int i = 0; i < 8; i++)
#pragma unroll
        for (int j = 0; j < 8; j++) acc[i][j] = 0.f;

    const float* Aptr = &g_spanvec[(size_t)(by*BM + arow) * D_];
    float4 pa = *(const float4*)&Aptr[acol];
    float4 pb = *(const float4*)&W1[(size_t)brow * D_ + bx*BN + bcol];

    const int iters = D_ / BK; // 288
    for (int kt = 0; kt < iters; kt++) {
        As[acol+0][arow] = pa.x;
        As[acol+1][arow] = pa.y;
        As[acol+2][arow] = pa.z;
        As[acol+3][arow] = pa.w;
        *(float4*)&Bs[brow][bcol] = pb;
        __syncthreads();
        if (kt + 1 < iters) {
            int k0 = (kt+1)*BK;
            pa = *(const float4*)&Aptr[k0 + acol];
            pb = *(const float4*)&W1[(size_t)(k0 + brow) * D_ + bx*BN + bcol];
        }
#pragma unroll
        for (int kk = 0; kk < BK; kk++) {
            float4 a0 = *(float4*)&As[kk][ty*4];
            float4 a1 = *(float4*)&As[kk][ty*4+64];
            float4 b0 = *(float4*)&Bs[kk][tx*4];
            float4 b1v = *(float4*)&Bs[kk][tx*4+64];
            float a[8] = {a0.x,a0.y,a0.z,a0.w,a1.x,a1.y,a1.z,a1.w};
            float b[8] = {b0.x,b0.y,b0.z,b0.w,b1v.x,b1v.y,b1v.z,b1v.w};
#pragma unroll
            for (int i = 0; i < 8; i++)
#pragma unroll
                for (int j = 0; j < 8; j++)
                    acc[i][j] += a[i]*b[j];
        }
        __syncthreads();
    }

    // epilogue: relu(acc + b1[c]) * W2[c], row-wise partial sum -> atomicAdd
#pragma unroll
    for (int i = 0; i < 8; i++) {
        int r = by*BM + ((i < 4) ? (ty*4 + i) : (64 + ty*4 + i - 4));
        if (r >= nspan) continue;
        float rsum = 0.f;
#pragma unroll
        for (int j = 0; j < 8; j++) {
            int c = bx*BN + ((j < 4) ? (tx*4 + j) : (64 + tx*4 + j - 4));
            float v = acc[i][j] + b1[c];
            v = v > 0.f ? v : 0.f;
            rsum += v * W2[c];
        }
        atomicAdd(&g_mscore[r], rsum);
    }
}

// ---------------- exact stable top-k by ranking --------------------------------
__global__ void topk_kernel(int nspan, int ktop) {
    __shared__ float sc[MAXSPAN];
    for (int i = threadIdx.x; i < MAXSPAN; i += blockDim.x)
        sc[i] = (i < nspan) ? g_mscore[i] : -3.4e38f;
    __syncthreads();
    int i = blockIdx.x * blockDim.x + threadIdx.x;
    if (i >= nspan) return;
    float si = sc[i];
    int r = 0;
    for (int j = 0; j < nspan; j++) {
        float sj = sc[j];
        r += (sj > si) || (sj == si && j < i);
    }
    if (r < ktop) g_topk[r] = i;
}

// ---------------- antecedent projections: s_i, s_j ------------------------------
__global__ void ant_proj_kernel(const float* __restrict__ antW, int ktop) {
    int b = blockIdx.x;
    int idx = g_topk[b];
    const float* row = &g_spanvec[(size_t)idx * D_];
    float si = 0.f, sj = 0.f;
    for (int c = threadIdx.x; c < D_; c += blockDim.x) {
        float v = row[c];
        si += v * antW[c];
        sj += v * antW[D_ + c];
    }
    __shared__ float r1[256], r2[256];
    r1[threadIdx.x] = si; r2[threadIdx.x] = sj;
    __syncthreads();
    for (int o = 128; o > 0; o >>= 1) {
        if (threadIdx.x < o) {
            r1[threadIdx.x] += r1[threadIdx.x + o];
            r2[threadIdx.x] += r2[threadIdx.x + o];
        }
        __syncthreads();
    }
    if (threadIdx.x == 0) { g_si[b] = r1[0]; g_sj[b] = r2[0]; }
}

// ---------------- final antecedent score matrix with dummy ----------------------
__global__ void final_kernel(float* __restrict__ out,
                             const float* __restrict__ ant_b, int ktop) {
    int id = blockIdx.x * blockDim.x + threadIdx.x;
    int total = ktop * (ktop + 1);
    if (id >= total) return;
    int i = id / (ktop + 1);
    int c = id % (ktop + 1);
    float v;
    if (c == 0) {
        v = 0.f;
    } else {
        int j = c - 1;
        v = (j >= i) ? -10000.0f : (g_si[i] + g_sj[j] + ant_b[0]);
    }
    out[id] = v;
}

// ---------------- host launch ---------------------------------------------------
extern "C" void kernel_launch(void* const* d_in, const int* in_sizes, int n_in,
                              void* d_out, int out_size) {
    const float* hidden = (const float*)d_in[0];
    const int*   edges  = (const int*)d_in[1];
    const float* gcnW   = (const float*)d_in[2];
    const float* gcnb   = (const float*)d_in[3];
    const float* attnw  = (const float*)d_in[4];
    const float* attnb  = (const float*)d_in[5];
    const float* msW1   = (const float*)d_in[6];
    const float* msb1   = (const float*)d_in[7];
    const float* msW2   = (const float*)d_in[8];
    const float* msb2   = (const float*)d_in[9];
    const float* antW   = (const float*)d_in[10];
    const float* antb   = (const float*)d_in[11];
    const int*   sstart = (const int*)d_in[12];
    const int*   send   = (const int*)d_in[13];

    int E = in_sizes[1] / 3;
    int nspan = in_sizes[12];
    // out_size = k*(k+1) -> derive k (topk) without a device read
    int ktop = (int)((sqrt(4.0 * (double)out_size + 1.0) - 1.0) / 2.0 + 0.5);
    float* out = (float*)d_out;

    zero_agg_kernel<<<2048, 256>>>();
    zero_small_kernel<<<512, 256>>>();
    scatter_kernel<<<E, 256>>>(hidden, edges);
    gemm_gcn_kernel<<<dim3(H_/BN, S_/BM, SPLITK), 256>>>(gcnW);
    gcn_finish_kernel<<<S_, 256>>>(hidden, gcnb);
    row_score_kernel<<<S_/8, 256>>>(attnw, attnb);
    span_kernel<<<(nspan*32 + 255)/256, 256>>>(sstart, send, nspan);
    init_mscore_kernel<<<(nspan + 255)/256, 256>>>(msb2, nspan);
    gemm_mention_kernel<<<dim3(D_/BN, MAXSPAN/BM), 256>>>(msW1, msb1, msW2, nspan);
    topk_kernel<<<(nspan + 255)/256, 256>>>(nspan, ktop);
    ant_proj_kernel<<<ktop, 256>>>(antW, ktop);
    final_kernel<<<(ktop*(ktop+1) + 255)/256, 256>>>(out, antb, ktop);
}